// round 15
// baseline (speedup 1.0000x reference)
#include <cuda_runtime.h>
#include <cuda_fp16.h>
#include <cstdint>
#include <math.h>

#define Bn      8
#define Nn      1024
#define DIMn    768
#define Hn      12
#define DHn     64
#define INNERn  768
#define NCn     2304
#define Mrows   (Bn * Nn)     // 8192
#define L2E     1.44269504088896f
#define QSCALE  (0.125f * L2E)   // softmax scale folded with log2e
#define SHIFTc  9.0f              // uniform log2-domain shift (cancels in norm)

// ---------------------------------------------------------------------------
// Scratch (allocation-free __device__ globals) — fp16
// ---------------------------------------------------------------------------
__device__ __half g_qh[Bn * Hn * Nn * DHn];  // [bh][i][d], scaled by 0.125*log2e
__device__ __half g_kh[Bn * Hn * Nn * DHn];  // [bh][j][d]
__device__ __half g_vh[Bn * Hn * Nn * DHn];  // [bh][j][d]  (row-major like K)
__device__ __half g_xh[Mrows * DIMn];
__device__ __half g_wqh[NCn * DIMn];         // w_qkv transposed [N][K]
__device__ __half g_woh[INNERn * DIMn];      // w_out transposed [N][K]
__device__ __half g_oh[Mrows * INNERn];

// ---------------------------------------------------------------------------
// Helpers
// ---------------------------------------------------------------------------
__device__ __forceinline__ uint32_t smem_u32(const void* p) {
    uint32_t a;
    asm("{ .reg .u64 t; cvta.to.shared.u64 t, %1; cvt.u32.u64 %0, t; }"
        : "=r"(a) : "l"(p));
    return a;
}

__device__ __forceinline__ void cp16(uint32_t s, const void* g) {
    asm volatile("cp.async.cg.shared.global [%0], [%1], 16;" :: "r"(s), "l"(g));
}
#define CP_COMMIT() asm volatile("cp.async.commit_group;" ::: "memory")
#define CP_WAIT(N)  asm volatile("cp.async.wait_group %0;" :: "n"(N) : "memory")

__device__ __forceinline__ void ldm_x4(uint32_t addr, uint32_t* r) {
    asm volatile(
        "ldmatrix.sync.aligned.m8n8.x4.shared.b16 {%0,%1,%2,%3}, [%4];"
        : "=r"(r[0]), "=r"(r[1]), "=r"(r[2]), "=r"(r[3]) : "r"(addr));
}

__device__ __forceinline__ void ldm_x4t(uint32_t addr, uint32_t* r) {
    asm volatile(
        "ldmatrix.sync.aligned.m8n8.x4.trans.shared.b16 {%0,%1,%2,%3}, [%4];"
        : "=r"(r[0]), "=r"(r[1]), "=r"(r[2]), "=r"(r[3]) : "r"(addr));
}

__device__ __forceinline__ void mma16816(float* d, const uint32_t* a,
                                         uint32_t b0, uint32_t b1) {
    asm volatile(
        "mma.sync.aligned.m16n8k16.row.col.f32.f16.f16.f32 "
        "{%0,%1,%2,%3}, {%4,%5,%6,%7}, {%8,%9}, {%0,%1,%2,%3};"
        : "+f"(d[0]), "+f"(d[1]), "+f"(d[2]), "+f"(d[3])
        : "r"(a[0]), "r"(a[1]), "r"(a[2]), "r"(a[3]), "r"(b0), "r"(b1));
}

__device__ __forceinline__ uint32_t pack_h2(float a, float b) {
    __half2 t = __floats2half2_rn(a, b);
    return *reinterpret_cast<uint32_t*>(&t);
}

__device__ __forceinline__ float ex2f(float x) {
    float r;
    asm("ex2.approx.f32 %0, %1;" : "=f"(r) : "f"(x));
    return r;
}

__device__ __forceinline__ uint32_t swz128(int row, int cbyte) {
    return (uint32_t)(row * 128 + (((cbyte >> 4) ^ (row & 7)) << 4) + (cbyte & 15));
}

// ---------------------------------------------------------------------------
// Fused prep: x fp32->fp16 convert + both weight transposes, one launch.
// ---------------------------------------------------------------------------
#define XB 6144   // (Mrows*DIMn/4)/256

__global__ __launch_bounds__(256) void prep(const float* __restrict__ x,
                                            __half* __restrict__ xh,
                                            const float* __restrict__ w_qkv,
                                            __half* __restrict__ wqh,
                                            const float* __restrict__ w_out,
                                            __half* __restrict__ woh) {
    const int bx = blockIdx.x;
    if (bx < XB) {
        int i = bx * 256 + threadIdx.x;
        float4 v = reinterpret_cast<const float4*>(x)[i];
        uint2 hp;
        hp.x = pack_h2(v.x, v.y);
        hp.y = pack_h2(v.z, v.w);
        reinterpret_cast<uint2*>(xh)[i] = hp;
        return;
    }
    int idx = bx - XB;
    const float* src;
    __half* dh;
    int N, nb, kb;
    if (idx < 1728) {               // w_qkv: 72 x 24 tiles
        src = w_qkv; dh = wqh; N = NCn;
        nb = idx % 72; kb = idx / 72;
    } else {                        // w_out: 24 x 24 tiles
        idx -= 1728;
        src = w_out; dh = woh; N = INNERn;
        nb = idx % 24; kb = idx / 24;
    }
    __shared__ float t[32][33];
    const int k0 = kb * 32, n0 = nb * 32;
    const int tx = threadIdx.x & 31, ty = threadIdx.x >> 5;
#pragma unroll
    for (int i = 0; i < 32; i += 8)
        t[ty + i][tx] = src[(size_t)(k0 + ty + i) * N + n0 + tx];
    __syncthreads();
#pragma unroll
    for (int i = 0; i < 32; i += 8) {
        float v = t[tx][ty + i];
        dh[(size_t)(n0 + ty + i) * DIMn + k0 + tx] = __float2half_rn(v);
    }
}

// ---------------------------------------------------------------------------
// fp16 single-pass GEMM via mma.sync + ldmatrix: C = Ah @ Bh^T
// CTA 128x128, BK=64 (12 iters), 8 warps (4x2), 2-stage cp.async ring.
// ---------------------------------------------------------------------------
#define PITCH 144
#define TILE_B (128 * PITCH)            // 18432
#define BUF_B (2 * TILE_B)              // 36864 per stage
#define GEMM_SMEM (2 * BUF_B)           // 73728

template <int MODE>
__global__ __launch_bounds__(256) void mma_gemm(
    const __half* __restrict__ Ah, const __half* __restrict__ Bh,
    float* __restrict__ C, const float* __restrict__ bias, int Ncol) {
    extern __shared__ char sm[];
    const int tid = threadIdx.x;
    const int wid = tid >> 5;
    const int lane = tid & 31;
    const int wr = wid >> 1;
    const int wc = wid & 1;

    const int bm0 = blockIdx.y * 128;
    const int bn0 = blockIdx.x * 128;
    const uint32_t sb = smem_u32(sm);

    const int rowa_off = (((lane >> 3) & 1) << 3) + (lane & 7);
    const int aboff = (lane >> 4) << 4;
    const int rowb_off = ((lane >> 4) << 3) + (lane & 7);
    const int bboff = ((lane >> 3) & 1) << 4;

    float acc[2][8][4] = {};

    auto load_tiles = [&](int it, int buf) {
        const int k0 = it * 64;
        const uint32_t base = sb + buf * BUF_B;
#pragma unroll
        for (int i = 0; i < 4; i++) {
            const int idx = tid + i * 256;
            const int row = idx >> 3;
            const int ch = idx & 7;
            const uint32_t so = row * PITCH + ch * 16;
            cp16(base + so, Ah + (size_t)(bm0 + row) * DIMn + k0 + ch * 8);
            cp16(base + TILE_B + so, Bh + (size_t)(bn0 + row) * DIMn + k0 + ch * 8);
        }
    };

    load_tiles(0, 0);
    CP_COMMIT();

    const int nIter = DIMn / 64;  // 12
    for (int it = 0; it < nIter; ++it) {
        if (it + 1 < nIter) {
            load_tiles(it + 1, (it + 1) & 1);
            CP_COMMIT();
            CP_WAIT(1);
        } else {
            CP_WAIT(0);
        }
        __syncthreads();

        const uint32_t base = sb + (it & 1) * BUF_B;

#pragma unroll
        for (int k16 = 0; k16 < 64; k16 += 16) {
            const int kbyte = k16 * 2;
            uint32_t ah[2][4];
#pragma unroll
            for (int mt = 0; mt < 2; mt++) {
                const int arow = wr * 32 + mt * 16 + rowa_off;
                ldm_x4(base + (uint32_t)(arow * PITCH + kbyte + aboff), ah[mt]);
            }
            uint32_t bhf[4][4];
#pragma unroll
            for (int p = 0; p < 4; p++) {
                const int brow = wc * 64 + p * 16 + rowb_off;
                ldm_x4(base + TILE_B + (uint32_t)(brow * PITCH + kbyte + bboff),
                       bhf[p]);
            }
#pragma unroll
            for (int p = 0; p < 4; p++)
#pragma unroll
                for (int mt = 0; mt < 2; mt++) {
                    mma16816(acc[mt][2 * p],     ah[mt], bhf[p][0], bhf[p][1]);
                    mma16816(acc[mt][2 * p + 1], ah[mt], bhf[p][2], bhf[p][3]);
                }
        }
        __syncthreads();
    }

    // ---- epilogue ----
#pragma unroll
    for (int mt = 0; mt < 2; mt++) {
        const int ra = bm0 + wr * 32 + mt * 16 + (lane >> 2);
        const int rb = ra + 8;
#pragma unroll
        for (int nt = 0; nt < 8; nt++) {
            const int n = bn0 + wc * 64 + nt * 8 + (lane & 3) * 2;
            if (MODE == 0) {
                const int which = n / INNERn;
                const int rem = n - which * INNERn;
                const int h = rem >> 6;
                const int d = rem & 63;
                const int ba = ra >> 10, ia = ra & 1023;
                const int bb = rb >> 10, ib = rb & 1023;
                float v00 = acc[mt][nt][0], v01 = acc[mt][nt][1];
                float v10 = acc[mt][nt][2], v11 = acc[mt][nt][3];
                if (which == 0) {
                    v00 *= QSCALE; v01 *= QSCALE; v10 *= QSCALE; v11 *= QSCALE;
                }
                __half* dst = (which == 0) ? g_qh : (which == 1) ? g_kh : g_vh;
                size_t i0 = ((size_t)(ba * Hn + h) * Nn + ia) * DHn + d;
                size_t i1 = ((size_t)(bb * Hn + h) * Nn + ib) * DHn + d;
                *reinterpret_cast<uint32_t*>(&dst[i0]) = pack_h2(v00, v01);
                *reinterpret_cast<uint32_t*>(&dst[i1]) = pack_h2(v10, v11);
            } else {
                const float b0 = bias[n], b1 = bias[n + 1];
                float2 v0 = {acc[mt][nt][0] + b0, acc[mt][nt][1] + b1};
                float2 v1 = {acc[mt][nt][2] + b0, acc[mt][nt][3] + b1};
                *(float2*)&C[(size_t)ra * Ncol + n] = v0;
                *(float2*)&C[(size_t)rb * Ncol + n] = v1;
            }
        }
    }
}

// ---------------------------------------------------------------------------
// Tensor-core flash attention: fp16, max-free log2-domain softmax (fp32 ex2).
// CTA = 256 q rows, 8 warps x 32 rows (2 m-tiles). V row-major, trans-ldmatrix.
// S restructured ntp-outer/kt-inner so each 16-key block's exp (MUFU) overlaps
// the next block's HMMA — cross-pipe ILP instead of serialized phases.
// ---------------------------------------------------------------------------
#define KVSTAGE 16384                 // KH 8K, VH 8K
#define OFF_QH 0                      // 32768 (256 rows x 128B)
#define OFF_KV 32768                  // 3 stages x 16384
#define OFF_BIAS (32768 + 3 * KVSTAGE)  // 81920, float2[2047] = 16376 B
#define ATT_SMEM (OFF_BIAS + 16384)     // 98304

__global__ __launch_bounds__(256) void attn_mma(const float* __restrict__ bias_table) {
    extern __shared__ char sm[];
    const uint32_t sb = smem_u32(sm);
    const int tid = threadIdx.x, wid = tid >> 5, lane = tid & 31;
    const int bh = blockIdx.y;
    const int b = bh / Hn, h = bh - b * Hn;
    const int q0 = blockIdx.x * 256;

    const __half* qhp = g_qh + (size_t)bh * Nn * DHn;
    const __half* khp = g_kh + (size_t)bh * Nn * DHn;
    const __half* vhp = g_vh + (size_t)bh * Nn * DHn;

    // Bias pairs: bp[m] = { r[m], r[m-1] }, r[m] = bias(off=m-1023)*log2e - 9
    float2* bp = (float2*)(sm + OFF_BIAS);
    const float* bt = bias_table + (size_t)h * (2 * Nn - 1);
    for (int m = tid; m < 2 * Nn - 1; m += 256) {
        float r0 = bt[m <= 1023 ? 1023 - m : m];
        float r1 = (m >= 1) ? bt[(m - 1) <= 1023 ? 1024 - m : (m - 1)] : 0.f;
        bp[m] = make_float2(r0 * L2E - SHIFTc, r1 * L2E - SHIFTc);
    }

    // Q tile: 256 rows x 64 d, swizzled (32KB)
#pragma unroll
    for (int i = 0; i < 8; i++) {
        const int idx = tid + i * 256;
        const int row = idx >> 3, ch = idx & 7;
        const uint32_t so = (uint32_t)(row * 128 + ((ch ^ (row & 7)) << 4));
        cp16(sb + OFF_QH + so, qhp + (size_t)(q0 + row) * DHn + ch * 8);
    }

    auto load_kv = [&](int tile, int buf) {
        const uint32_t kb = sb + OFF_KV + buf * KVSTAGE;
        const int kv0 = tile * 64;
#pragma unroll
        for (int i = 0; i < 2; i++) {
            const int idx = tid + i * 256;
            const int row = idx >> 3, ch = idx & 7;
            const uint32_t so = (uint32_t)(row * 128 + ((ch ^ (row & 7)) << 4));
            cp16(kb + so,        khp + (size_t)(kv0 + row) * DHn + ch * 8);
            cp16(kb + 8192 + so, vhp + (size_t)(kv0 + row) * DHn + ch * 8);
        }
    };

    load_kv(0, 0);
    CP_COMMIT();

    const int rl = lane >> 2;
    const int c2 = (lane & 3) * 2;
    const int rowk_base = ((lane >> 4) << 3) + (lane & 7);
    const int kboff = ((lane >> 3) & 1) << 4;
    const int rowq_off = (((lane >> 3) & 1) << 3) + (lane & 7);
    const int qboff = (lane >> 4) << 4;

    // Hoisted per-thread fragment offsets (within a KV stage)
    uint32_t koff[16], voff[16];
#pragma unroll
    for (int kt = 0; kt < 4; kt++)
#pragma unroll
        for (int ntp = 0; ntp < 4; ntp++) {
            koff[kt * 4 + ntp] = swz128(ntp * 16 + rowk_base, kt * 32 + kboff);
            voff[kt * 4 + ntp] = 8192u + swz128(kt * 16 + rowq_off, ntp * 32 + qboff);
        }

    int gi_lo[2];
#pragma unroll
    for (int mt = 0; mt < 2; mt++) gi_lo[mt] = q0 + wid * 32 + mt * 16 + rl;

    float l_lo[2] = {0.f, 0.f}, l_hi[2] = {0.f, 0.f};
    float acc[2][8][4] = {};
    uint32_t qhf[2][4][4];

    for (int t = 0; t < 16; t++) {
        if (t + 1 < 16) {
            load_kv(t + 1, (t + 1) % 3);
            CP_COMMIT();
            CP_WAIT(1);
        } else {
            CP_WAIT(0);
        }
        __syncthreads();

        if (t == 0) {
#pragma unroll
            for (int mt = 0; mt < 2; mt++)
#pragma unroll
                for (int kt = 0; kt < 4; kt++) {
                    const int row = wid * 32 + mt * 16 + rowq_off;
                    ldm_x4(sb + OFF_QH + swz128(row, kt * 32 + qboff), qhf[mt][kt]);
                }
        }

        const uint32_t kb = sb + OFF_KV + (t % 3) * KVSTAGE;

        // ---- S + exp interleaved per 16-key block (ntp) ----
        // Each ntp block: 16 HMMA then 8 exp — MUFU of block n overlaps
        // HMMA of block n+1 (independent registers, fully unrolled).
        uint32_t pe[2][8][2];
#pragma unroll
        for (int ntp = 0; ntp < 4; ntp++) {
            float pcl[2][2][4] = {};   // this block's logits [mt][sub][4]
#pragma unroll
            for (int kt = 0; kt < 4; kt++) {
                uint32_t kh[4];
                ldm_x4(kb + koff[kt * 4 + ntp], kh);
#pragma unroll
                for (int mt = 0; mt < 2; mt++) {
                    mma16816(pcl[mt][0], qhf[mt][kt], kh[0], kh[1]);
                    mma16816(pcl[mt][1], qhf[mt][kt], kh[2], kh[3]);
                }
            }
#pragma unroll
            for (int mt = 0; mt < 2; mt++) {
                const int mlo0 = gi_lo[mt] + 1023 - t * 64 - c2;
                const int mhi0 = mlo0 + 8;
#pragma unroll
                for (int s = 0; s < 2; s++) {
                    const int nt = 2 * ntp + s;
                    float2 blo = bp[mlo0 - 8 * nt];
                    float2 bhi = bp[mhi0 - 8 * nt];
                    float e0 = ex2f(pcl[mt][s][0] + blo.x);
                    float e1 = ex2f(pcl[mt][s][1] + blo.y);
                    float e2 = ex2f(pcl[mt][s][2] + bhi.x);
                    float e3 = ex2f(pcl[mt][s][3] + bhi.y);
                    pe[mt][nt][0] = pack_h2(e0, e1);
                    pe[mt][nt][1] = pack_h2(e2, e3);
                    if (mt == 0) { l_lo[0] += e0 + e1; l_hi[0] += e2 + e3; }
                    else         { l_lo[1] += e0 + e1; l_hi[1] += e2 + e3; }
                }
            }
        }

        // ---- O += P @ V (V via trans-ldmatrix, hoisted offsets) ----
#pragma unroll
        for (int kt = 0; kt < 4; kt++) {
            uint32_t ph[2][4];
#pragma unroll
            for (int mt = 0; mt < 2; mt++) {
                ph[mt][0] = pe[mt][2 * kt][0];
                ph[mt][1] = pe[mt][2 * kt][1];
                ph[mt][2] = pe[mt][2 * kt + 1][0];
                ph[mt][3] = pe[mt][2 * kt + 1][1];
            }
#pragma unroll
            for (int ntp = 0; ntp < 4; ntp++) {
                uint32_t vh[4];
                ldm_x4t(kb + voff[kt * 4 + ntp], vh);
#pragma unroll
                for (int mt = 0; mt < 2; mt++) {
                    mma16816(acc[mt][2 * ntp],     ph[mt], vh[0], vh[1]);
                    mma16816(acc[mt][2 * ntp + 1], ph[mt], vh[2], vh[3]);
                }
            }
        }
    }

    // ---- epilogue: quad-reduce l, normalize, write O (fp16) ----
#pragma unroll
    for (int mt = 0; mt < 2; mt++) {
        l_lo[mt] += __shfl_xor_sync(0xffffffffu, l_lo[mt], 1);
        l_lo[mt] += __shfl_xor_sync(0xffffffffu, l_lo[mt], 2);
        l_hi[mt] += __shfl_xor_sync(0xffffffffu, l_hi[mt], 1);
        l_hi[mt] += __shfl_xor_sync(0xffffffffu, l_hi[mt], 2);
        const float inv_lo = 1.f / l_lo[mt];
        const float inv_hi = 1.f / l_hi[mt];
#pragma unroll
        for (int nt = 0; nt < 8; nt++) {
            const int d = nt * 8 + c2;
            size_t i0 = (size_t)(b * Nn + gi_lo[mt]) * INNERn + h * DHn + d;
            *reinterpret_cast<uint32_t*>(&g_oh[i0]) =
                pack_h2(acc[mt][nt][0] * inv_lo, acc[mt][nt][1] * inv_lo);
            size_t i1 = (size_t)(b * Nn + gi_lo[mt] + 8) * INNERn + h * DHn + d;
            *reinterpret_cast<uint32_t*>(&g_oh[i1]) =
                pack_h2(acc[mt][nt][2] * inv_hi, acc[mt][nt][3] * inv_hi);
        }
    }
}

// ---------------------------------------------------------------------------
extern "C" void kernel_launch(void* const* d_in, const int* in_sizes, int n_in,
                              void* d_out, int out_size) {
    const float* x          = (const float*)d_in[0];
    const float* w_qkv      = (const float*)d_in[1];
    const float* bias_table = (const float*)d_in[2];
    const float* w_out      = (const float*)d_in[3];
    const float* b_out      = (const float*)d_in[4];
    float* out = (float*)d_out;

    cudaFuncSetAttribute(attn_mma, cudaFuncAttributeMaxDynamicSharedMemorySize,
                         ATT_SMEM);
    cudaFuncSetAttribute(mma_gemm<0>, cudaFuncAttributeMaxDynamicSharedMemorySize,
                         GEMM_SMEM);
    cudaFuncSetAttribute(mma_gemm<1>, cudaFuncAttributeMaxDynamicSharedMemorySize,
                         GEMM_SMEM);

    __half *xh, *wqh, *woh, *oh;
    cudaGetSymbolAddress((void**)&xh, g_xh);
    cudaGetSymbolAddress((void**)&wqh, g_wqh);
    cudaGetSymbolAddress((void**)&woh, g_woh);
    cudaGetSymbolAddress((void**)&oh, g_oh);

    // 0) fused prep: x convert + both weight transposes (one launch)
    prep<<<XB + 1728 + 576, 256>>>(x, xh, w_qkv, wqh, w_out, woh);

    // 1) QKV projection (single-pass fp16, BK=64) -> q/k/v fp16 (coalesced)
    dim3 g1(NCn / 128, Mrows / 128);
    mma_gemm<0><<<g1, 256, GEMM_SMEM>>>(xh, wqh, nullptr, nullptr, NCn);

    // 2) Tensor-core flash attention (S/exp interleaved per 16-key block)
    dim3 g2(Nn / 256, Bn * Hn);
    attn_mma<<<g2, 256, ATT_SMEM>>>(bias_table);

    // 3) Output projection (single-pass fp16, BK=64) + bias
    dim3 g3(INNERn / 128, Mrows / 128);
    mma_gemm<1><<<g3, 256, GEMM_SMEM>>>(oh, woh, out, b_out, INNERn);
}

// round 16
// speedup vs baseline: 1.0260x; 1.0260x over previous
#include <cuda_runtime.h>
#include <cuda_fp16.h>
#include <cstdint>
#include <math.h>

#define Bn      8
#define Nn      1024
#define DIMn    768
#define Hn      12
#define DHn     64
#define INNERn  768
#define NCn     2304
#define Mrows   (Bn * Nn)     // 8192
#define L2E     1.44269504088896f
#define QSCALE  (0.125f * L2E)
#define SHIFTc  9.0f

// ---------------------------------------------------------------------------
// Scratch (allocation-free __device__ globals) — fp16
// ---------------------------------------------------------------------------
__device__ __half g_qh[Bn * Hn * Nn * DHn];
__device__ __half g_kh[Bn * Hn * Nn * DHn];
__device__ __half g_vh[Bn * Hn * Nn * DHn];
__device__ __half g_xh[Mrows * DIMn];
__device__ __half g_wqh[NCn * DIMn];
__device__ __half g_woh[INNERn * DIMn];
__device__ __half g_oh[Mrows * INNERn];

// ---------------------------------------------------------------------------
// Helpers
// ---------------------------------------------------------------------------
__device__ __forceinline__ uint32_t smem_u32(const void* p) {
    uint32_t a;
    asm("{ .reg .u64 t; cvta.to.shared.u64 t, %1; cvt.u32.u64 %0, t; }"
        : "=r"(a) : "l"(p));
    return a;
}

__device__ __forceinline__ void cp16(uint32_t s, const void* g) {
    asm volatile("cp.async.cg.shared.global [%0], [%1], 16;" :: "r"(s), "l"(g));
}
#define CP_COMMIT() asm volatile("cp.async.commit_group;" ::: "memory")
#define CP_WAIT(N)  asm volatile("cp.async.wait_group %0;" :: "n"(N) : "memory")

__device__ __forceinline__ void ldm_x4(uint32_t addr, uint32_t* r) {
    asm volatile(
        "ldmatrix.sync.aligned.m8n8.x4.shared.b16 {%0,%1,%2,%3}, [%4];"
        : "=r"(r[0]), "=r"(r[1]), "=r"(r[2]), "=r"(r[3]) : "r"(addr));
}

__device__ __forceinline__ void ldm_x4t(uint32_t addr, uint32_t* r) {
    asm volatile(
        "ldmatrix.sync.aligned.m8n8.x4.trans.shared.b16 {%0,%1,%2,%3}, [%4];"
        : "=r"(r[0]), "=r"(r[1]), "=r"(r[2]), "=r"(r[3]) : "r"(addr));
}

__device__ __forceinline__ void mma16816(float* d, const uint32_t* a,
                                         uint32_t b0, uint32_t b1) {
    asm volatile(
        "mma.sync.aligned.m16n8k16.row.col.f32.f16.f16.f32 "
        "{%0,%1,%2,%3}, {%4,%5,%6,%7}, {%8,%9}, {%0,%1,%2,%3};"
        : "+f"(d[0]), "+f"(d[1]), "+f"(d[2]), "+f"(d[3])
        : "r"(a[0]), "r"(a[1]), "r"(a[2]), "r"(a[3]), "r"(b0), "r"(b1));
}

__device__ __forceinline__ uint32_t pack_h2(float a, float b) {
    __half2 t = __floats2half2_rn(a, b);
    return *reinterpret_cast<uint32_t*>(&t);
}

__device__ __forceinline__ float ex2f(float x) {
    float r;
    asm("ex2.approx.f32 %0, %1;" : "=f"(r) : "f"(x));
    return r;
}

__device__ __forceinline__ uint32_t swz128(int row, int cbyte) {
    return (uint32_t)(row * 128 + (((cbyte >> 4) ^ (row & 7)) << 4) + (cbyte & 15));
}

// ---------------------------------------------------------------------------
// Fused prep: x fp32->fp16 convert + both weight transposes, one launch.
// ---------------------------------------------------------------------------
#define XB 6144   // (Mrows*DIMn/4)/256

__global__ __launch_bounds__(256) void prep(const float* __restrict__ x,
                                            __half* __restrict__ xh,
                                            const float* __restrict__ w_qkv,
                                            __half* __restrict__ wqh,
                                            const float* __restrict__ w_out,
                                            __half* __restrict__ woh) {
    const int bx = blockIdx.x;
    if (bx < XB) {
        int i = bx * 256 + threadIdx.x;
        float4 v = reinterpret_cast<const float4*>(x)[i];
        uint2 hp;
        hp.x = pack_h2(v.x, v.y);
        hp.y = pack_h2(v.z, v.w);
        reinterpret_cast<uint2*>(xh)[i] = hp;
        return;
    }
    int idx = bx - XB;
    const float* src;
    __half* dh;
    int N, nb, kb;
    if (idx < 1728) {
        src = w_qkv; dh = wqh; N = NCn;
        nb = idx % 72; kb = idx / 72;
    } else {
        idx -= 1728;
        src = w_out; dh = woh; N = INNERn;
        nb = idx % 24; kb = idx / 24;
    }
    __shared__ float t[32][33];
    const int k0 = kb * 32, n0 = nb * 32;
    const int tx = threadIdx.x & 31, ty = threadIdx.x >> 5;
#pragma unroll
    for (int i = 0; i < 32; i += 8)
        t[ty + i][tx] = src[(size_t)(k0 + ty + i) * N + n0 + tx];
    __syncthreads();
#pragma unroll
    for (int i = 0; i < 32; i += 8) {
        float v = t[tx][ty + i];
        dh[(size_t)(n0 + ty + i) * DIMn + k0 + tx] = __float2half_rn(v);
    }
}

// ---------------------------------------------------------------------------
// QKV GEMM: CTA 128x128, BK=64, 8 warps (4x2), 2-stage ring (R14-proven).
// ---------------------------------------------------------------------------
#define PITCH 144
#define TILE_B (128 * PITCH)            // 18432
#define BUF_B (2 * TILE_B)              // 36864 per stage
#define GEMM_SMEM (2 * BUF_B)           // 73728

__global__ __launch_bounds__(256) void mma_qkv(
    const __half* __restrict__ Ah, const __half* __restrict__ Bh) {
    extern __shared__ char sm[];
    const int tid = threadIdx.x;
    const int wid = tid >> 5;
    const int lane = tid & 31;
    const int wr = wid >> 1;
    const int wc = wid & 1;

    const int bm0 = blockIdx.y * 128;
    const int bn0 = blockIdx.x * 128;
    const uint32_t sb = smem_u32(sm);

    const int rowa_off = (((lane >> 3) & 1) << 3) + (lane & 7);
    const int aboff = (lane >> 4) << 4;
    const int rowb_off = ((lane >> 4) << 3) + (lane & 7);
    const int bboff = ((lane >> 3) & 1) << 4;

    float acc[2][8][4] = {};

    auto load_tiles = [&](int it, int buf) {
        const int k0 = it * 64;
        const uint32_t base = sb + buf * BUF_B;
#pragma unroll
        for (int i = 0; i < 4; i++) {
            const int idx = tid + i * 256;
            const int row = idx >> 3;
            const int ch = idx & 7;
            const uint32_t so = row * PITCH + ch * 16;
            cp16(base + so, Ah + (size_t)(bm0 + row) * DIMn + k0 + ch * 8);
            cp16(base + TILE_B + so, Bh + (size_t)(bn0 + row) * DIMn + k0 + ch * 8);
        }
    };

    load_tiles(0, 0);
    CP_COMMIT();

    const int nIter = DIMn / 64;  // 12
    for (int it = 0; it < nIter; ++it) {
        if (it + 1 < nIter) {
            load_tiles(it + 1, (it + 1) & 1);
            CP_COMMIT();
            CP_WAIT(1);
        } else {
            CP_WAIT(0);
        }
        __syncthreads();

        const uint32_t base = sb + (it & 1) * BUF_B;

#pragma unroll
        for (int k16 = 0; k16 < 64; k16 += 16) {
            const int kbyte = k16 * 2;
            uint32_t ah[2][4];
#pragma unroll
            for (int mt = 0; mt < 2; mt++) {
                const int arow = wr * 32 + mt * 16 + rowa_off;
                ldm_x4(base + (uint32_t)(arow * PITCH + kbyte + aboff), ah[mt]);
            }
            uint32_t bhf[4][4];
#pragma unroll
            for (int p = 0; p < 4; p++) {
                const int brow = wc * 64 + p * 16 + rowb_off;
                ldm_x4(base + TILE_B + (uint32_t)(brow * PITCH + kbyte + bboff),
                       bhf[p]);
            }
#pragma unroll
            for (int p = 0; p < 4; p++)
#pragma unroll
                for (int mt = 0; mt < 2; mt++) {
                    mma16816(acc[mt][2 * p],     ah[mt], bhf[p][0], bhf[p][1]);
                    mma16816(acc[mt][2 * p + 1], ah[mt], bhf[p][2], bhf[p][3]);
                }
        }
        __syncthreads();
    }

    // ---- epilogue: scatter q/k/v ----
#pragma unroll
    for (int mt = 0; mt < 2; mt++) {
        const int ra = bm0 + wr * 32 + mt * 16 + (lane >> 2);
        const int rb = ra + 8;
#pragma unroll
        for (int nt = 0; nt < 8; nt++) {
            const int n = bn0 + wc * 64 + nt * 8 + (lane & 3) * 2;
            const int which = n / INNERn;
            const int rem = n - which * INNERn;
            const int h = rem >> 6;
            const int d = rem & 63;
            const int ba = ra >> 10, ia = ra & 1023;
            const int bb = rb >> 10, ib = rb & 1023;
            float v00 = acc[mt][nt][0], v01 = acc[mt][nt][1];
            float v10 = acc[mt][nt][2], v11 = acc[mt][nt][3];
            if (which == 0) {
                v00 *= QSCALE; v01 *= QSCALE; v10 *= QSCALE; v11 *= QSCALE;
            }
            __half* dst = (which == 0) ? g_qh : (which == 1) ? g_kh : g_vh;
            size_t i0 = ((size_t)(ba * Hn + h) * Nn + ia) * DHn + d;
            size_t i1 = ((size_t)(bb * Hn + h) * Nn + ib) * DHn + d;
            *reinterpret_cast<uint32_t*>(&dst[i0]) = pack_h2(v00, v01);
            *reinterpret_cast<uint32_t*>(&dst[i1]) = pack_h2(v10, v11);
        }
    }
}

// ---------------------------------------------------------------------------
// Out-proj GEMM: CTA 128x192 -> grid 64x4 = 256 CTAs = ONE wave at 2 CTAs/SM
// (eliminates the 2-wave quantization of the 128x128 tiling). BK=64.
// 8 warps as 4(M) x 2(N); warp tile 32 x 96 (12 n8 fragments).
// Per-element accumulation order identical to 128x128 tiling (bitwise same C).
// ---------------------------------------------------------------------------
#define BTILE1_B (192 * PITCH)          // 27648
#define STAGE1_B (TILE_B + BTILE1_B)    // 46080
#define OUT_SMEM (2 * STAGE1_B)         // 92160

__global__ __launch_bounds__(256, 2) void mma_out(
    const __half* __restrict__ Ah, const __half* __restrict__ Bh,
    float* __restrict__ C, const float* __restrict__ bias) {
    extern __shared__ char sm[];
    const int tid = threadIdx.x;
    const int wid = tid >> 5;
    const int lane = tid & 31;
    const int wr = wid >> 1;   // 0..3 (M)
    const int wc = wid & 1;    // 0..1 (N)

    const int bm0 = blockIdx.y * 128;
    const int bn0 = blockIdx.x * 192;
    const uint32_t sb = smem_u32(sm);

    const int rowa_off = (((lane >> 3) & 1) << 3) + (lane & 7);
    const int aboff = (lane >> 4) << 4;
    const int rowb_off = ((lane >> 4) << 3) + (lane & 7);
    const int bboff = ((lane >> 3) & 1) << 4;

    float acc[2][12][4] = {};

    auto load_tiles = [&](int it, int buf) {
        const int k0 = it * 64;
        const uint32_t base = sb + buf * STAGE1_B;
#pragma unroll
        for (int i = 0; i < 10; i++) {
            const int idx = tid + i * 256;       // 0..2559
            if (idx < 1024) {                    // A: 128 rows x 8 chunks
                const int row = idx >> 3, ch = idx & 7;
                cp16(base + row * PITCH + ch * 16,
                     Ah + (size_t)(bm0 + row) * DIMn + k0 + ch * 8);
            } else {                             // B: 192 rows x 8 chunks
                const int j = idx - 1024;
                const int row = j >> 3, ch = j & 7;
                cp16(base + TILE_B + row * PITCH + ch * 16,
                     Bh + (size_t)(bn0 + row) * DIMn + k0 + ch * 8);
            }
        }
    };

    load_tiles(0, 0);
    CP_COMMIT();

    const int nIter = DIMn / 64;  // 12
    for (int it = 0; it < nIter; ++it) {
        if (it + 1 < nIter) {
            load_tiles(it + 1, (it + 1) & 1);
            CP_COMMIT();
            CP_WAIT(1);
        } else {
            CP_WAIT(0);
        }
        __syncthreads();

        const uint32_t base = sb + (it & 1) * STAGE1_B;

#pragma unroll
        for (int k16 = 0; k16 < 64; k16 += 16) {
            const int kbyte = k16 * 2;
            uint32_t ah[2][4];
#pragma unroll
            for (int mt = 0; mt < 2; mt++) {
                const int arow = wr * 32 + mt * 16 + rowa_off;
                ldm_x4(base + (uint32_t)(arow * PITCH + kbyte + aboff), ah[mt]);
            }
#pragma unroll
            for (int p = 0; p < 6; p++) {
                const int brow = wc * 96 + p * 16 + rowb_off;
                uint32_t bf[4];
                ldm_x4(base + TILE_B + (uint32_t)(brow * PITCH + kbyte + bboff), bf);
#pragma unroll
                for (int mt = 0; mt < 2; mt++) {
                    mma16816(acc[mt][2 * p],     ah[mt], bf[0], bf[1]);
                    mma16816(acc[mt][2 * p + 1], ah[mt], bf[2], bf[3]);
                }
            }
        }
        __syncthreads();
    }

    // ---- epilogue: C = acc + bias ----
#pragma unroll
    for (int mt = 0; mt < 2; mt++) {
        const int ra = bm0 + wr * 32 + mt * 16 + (lane >> 2);
        const int rb = ra + 8;
#pragma unroll
        for (int nt = 0; nt < 12; nt++) {
            const int n = bn0 + wc * 96 + nt * 8 + (lane & 3) * 2;
            const float b0 = bias[n], b1 = bias[n + 1];
            float2 v0 = {acc[mt][nt][0] + b0, acc[mt][nt][1] + b1};
            float2 v1 = {acc[mt][nt][2] + b0, acc[mt][nt][3] + b1};
            *(float2*)&C[(size_t)ra * INNERn + n] = v0;
            *(float2*)&C[(size_t)rb * INNERn + n] = v1;
        }
    }
}

// ---------------------------------------------------------------------------
// Tensor-core flash attention (R14-proven): fp16, max-free log2-domain softmax
// (fp32 ex2), CTA = 256 q rows, 8 warps x 32 rows, V row-major trans-ldmatrix,
// hoisted fragment offsets, fp32 scalar l partials + epilogue quad-shuffle.
// ---------------------------------------------------------------------------
#define KVSTAGE 16384
#define OFF_QH 0
#define OFF_KV 32768
#define OFF_BIAS (32768 + 3 * KVSTAGE)
#define ATT_SMEM (OFF_BIAS + 16384)

__global__ __launch_bounds__(256) void attn_mma(const float* __restrict__ bias_table) {
    extern __shared__ char sm[];
    const uint32_t sb = smem_u32(sm);
    const int tid = threadIdx.x, wid = tid >> 5, lane = tid & 31;
    const int bh = blockIdx.y;
    const int b = bh / Hn, h = bh - b * Hn;
    const int q0 = blockIdx.x * 256;

    const __half* qhp = g_qh + (size_t)bh * Nn * DHn;
    const __half* khp = g_kh + (size_t)bh * Nn * DHn;
    const __half* vhp = g_vh + (size_t)bh * Nn * DHn;

    float2* bp = (float2*)(sm + OFF_BIAS);
    const float* bt = bias_table + (size_t)h * (2 * Nn - 1);
    for (int m = tid; m < 2 * Nn - 1; m += 256) {
        float r0 = bt[m <= 1023 ? 1023 - m : m];
        float r1 = (m >= 1) ? bt[(m - 1) <= 1023 ? 1024 - m : (m - 1)] : 0.f;
        bp[m] = make_float2(r0 * L2E - SHIFTc, r1 * L2E - SHIFTc);
    }

#pragma unroll
    for (int i = 0; i < 8; i++) {
        const int idx = tid + i * 256;
        const int row = idx >> 3, ch = idx & 7;
        const uint32_t so = (uint32_t)(row * 128 + ((ch ^ (row & 7)) << 4));
        cp16(sb + OFF_QH + so, qhp + (size_t)(q0 + row) * DHn + ch * 8);
    }

    auto load_kv = [&](int tile, int buf) {
        const uint32_t kb = sb + OFF_KV + buf * KVSTAGE;
        const int kv0 = tile * 64;
#pragma unroll
        for (int i = 0; i < 2; i++) {
            const int idx = tid + i * 256;
            const int row = idx >> 3, ch = idx & 7;
            const uint32_t so = (uint32_t)(row * 128 + ((ch ^ (row & 7)) << 4));
            cp16(kb + so,        khp + (size_t)(kv0 + row) * DHn + ch * 8);
            cp16(kb + 8192 + so, vhp + (size_t)(kv0 + row) * DHn + ch * 8);
        }
    };

    load_kv(0, 0);
    CP_COMMIT();

    const int rl = lane >> 2;
    const int c2 = (lane & 3) * 2;
    const int rowk_base = ((lane >> 4) << 3) + (lane & 7);
    const int kboff = ((lane >> 3) & 1) << 4;
    const int rowq_off = (((lane >> 3) & 1) << 3) + (lane & 7);
    const int qboff = (lane >> 4) << 4;

    uint32_t koff[16], voff[16];
#pragma unroll
    for (int kt = 0; kt < 4; kt++)
#pragma unroll
        for (int ntp = 0; ntp < 4; ntp++) {
            koff[kt * 4 + ntp] = swz128(ntp * 16 + rowk_base, kt * 32 + kboff);
            voff[kt * 4 + ntp] = 8192u + swz128(kt * 16 + rowq_off, ntp * 32 + qboff);
        }

    int gi_lo[2];
#pragma unroll
    for (int mt = 0; mt < 2; mt++) gi_lo[mt] = q0 + wid * 32 + mt * 16 + rl;

    float l_lo[2] = {0.f, 0.f}, l_hi[2] = {0.f, 0.f};
    float acc[2][8][4] = {};
    uint32_t qhf[2][4][4];

    for (int t = 0; t < 16; t++) {
        if (t + 1 < 16) {
            load_kv(t + 1, (t + 1) % 3);
            CP_COMMIT();
            CP_WAIT(1);
        } else {
            CP_WAIT(0);
        }
        __syncthreads();

        if (t == 0) {
#pragma unroll
            for (int mt = 0; mt < 2; mt++)
#pragma unroll
                for (int kt = 0; kt < 4; kt++) {
                    const int row = wid * 32 + mt * 16 + rowq_off;
                    ldm_x4(sb + OFF_QH + swz128(row, kt * 32 + qboff), qhf[mt][kt]);
                }
        }

        const uint32_t kb = sb + OFF_KV + (t % 3) * KVSTAGE;

        // ---- S = Q @ K^T ----
        float pc[2][8][4] = {};
#pragma unroll
        for (int kt = 0; kt < 4; kt++) {
#pragma unroll
            for (int ntp = 0; ntp < 4; ntp++) {
                uint32_t kh[4];
                ldm_x4(kb + koff[kt * 4 + ntp], kh);
#pragma unroll
                for (int mt = 0; mt < 2; mt++) {
                    mma16816(pc[mt][2 * ntp],     qhf[mt][kt], kh[0], kh[1]);
                    mma16816(pc[mt][2 * ntp + 1], qhf[mt][kt], kh[2], kh[3]);
                }
            }
        }

        // ---- bias-pair add + fp32 ex2, pack fp16, accumulate l ----
        uint32_t pe[2][8][2];
#pragma unroll
        for (int mt = 0; mt < 2; mt++) {
            const int mlo0 = gi_lo[mt] + 1023 - t * 64 - c2;
            const int mhi0 = mlo0 + 8;
            float s_lo = 0.f, s_hi = 0.f;
#pragma unroll
            for (int nt = 0; nt < 8; nt++) {
                float2 blo = bp[mlo0 - 8 * nt];
                float2 bhi = bp[mhi0 - 8 * nt];
                float e0 = ex2f(pc[mt][nt][0] + blo.x);
                float e1 = ex2f(pc[mt][nt][1] + blo.y);
                float e2 = ex2f(pc[mt][nt][2] + bhi.x);
                float e3 = ex2f(pc[mt][nt][3] + bhi.y);
                pe[mt][nt][0] = pack_h2(e0, e1);
                pe[mt][nt][1] = pack_h2(e2, e3);
                s_lo += e0 + e1;
                s_hi += e2 + e3;
            }
            l_lo[mt] += s_lo;
            l_hi[mt] += s_hi;
        }

        // ---- O += P @ V ----
#pragma unroll
        for (int kt = 0; kt < 4; kt++) {
            uint32_t ph[2][4];
#pragma unroll
            for (int mt = 0; mt < 2; mt++) {
                ph[mt][0] = pe[mt][2 * kt][0];
                ph[mt][1] = pe[mt][2 * kt][1];
                ph[mt][2] = pe[mt][2 * kt + 1][0];
                ph[mt][3] = pe[mt][2 * kt + 1][1];
            }
#pragma unroll
            for (int ntp = 0; ntp < 4; ntp++) {
                uint32_t vh[4];
                ldm_x4t(kb + voff[kt * 4 + ntp], vh);
#pragma unroll
                for (int mt = 0; mt < 2; mt++) {
                    mma16816(acc[mt][2 * ntp],     ph[mt], vh[0], vh[1]);
                    mma16816(acc[mt][2 * ntp + 1], ph[mt], vh[2], vh[3]);
                }
            }
        }
    }

    // ---- epilogue ----
#pragma unroll
    for (int mt = 0; mt < 2; mt++) {
        l_lo[mt] += __shfl_xor_sync(0xffffffffu, l_lo[mt], 1);
        l_lo[mt] += __shfl_xor_sync(0xffffffffu, l_lo[mt], 2);
        l_hi[mt] += __shfl_xor_sync(0xffffffffu, l_hi[mt], 1);
        l_hi[mt] += __shfl_xor_sync(0xffffffffu, l_hi[mt], 2);
        const float inv_lo = 1.f / l_lo[mt];
        const float inv_hi = 1.f / l_hi[mt];
#pragma unroll
        for (int nt = 0; nt < 8; nt++) {
            const int d = nt * 8 + c2;
            size_t i0 = (size_t)(b * Nn + gi_lo[mt]) * INNERn + h * DHn + d;
            *reinterpret_cast<uint32_t*>(&g_oh[i0]) =
                pack_h2(acc[mt][nt][0] * inv_lo, acc[mt][nt][1] * inv_lo);
            size_t i1 = (size_t)(b * Nn + gi_lo[mt] + 8) * INNERn + h * DHn + d;
            *reinterpret_cast<uint32_t*>(&g_oh[i1]) =
                pack_h2(acc[mt][nt][2] * inv_hi, acc[mt][nt][3] * inv_hi);
        }
    }
}

// ---------------------------------------------------------------------------
extern "C" void kernel_launch(void* const* d_in, const int* in_sizes, int n_in,
                              void* d_out, int out_size) {
    const float* x          = (const float*)d_in[0];
    const float* w_qkv      = (const float*)d_in[1];
    const float* bias_table = (const float*)d_in[2];
    const float* w_out      = (const float*)d_in[3];
    const float* b_out      = (const float*)d_in[4];
    float* out = (float*)d_out;

    cudaFuncSetAttribute(attn_mma, cudaFuncAttributeMaxDynamicSharedMemorySize,
                         ATT_SMEM);
    cudaFuncSetAttribute(mma_qkv, cudaFuncAttributeMaxDynamicSharedMemorySize,
                         GEMM_SMEM);
    cudaFuncSetAttribute(mma_out, cudaFuncAttributeMaxDynamicSharedMemorySize,
                         OUT_SMEM);

    __half *xh, *wqh, *woh, *oh;
    cudaGetSymbolAddress((void**)&xh, g_xh);
    cudaGetSymbolAddress((void**)&wqh, g_wqh);
    cudaGetSymbolAddress((void**)&woh, g_woh);
    cudaGetSymbolAddress((void**)&oh, g_oh);

    // 0) fused prep: x convert + both weight transposes (one launch)
    prep<<<XB + 1728 + 576, 256>>>(x, xh, w_qkv, wqh, w_out, woh);

    // 1) QKV projection (128x128 tiles, 1152 CTAs)
    dim3 g1(NCn / 128, Mrows / 128);
    mma_qkv<<<g1, 256, GEMM_SMEM>>>(xh, wqh);

    // 2) Tensor-core flash attention (R14 configuration)
    dim3 g2(Nn / 256, Bn * Hn);
    attn_mma<<<g2, 256, ATT_SMEM>>>(bias_table);

    // 3) Output projection: 128x192 tiles -> 256 CTAs = one wave
    dim3 g3(INNERn / 192, Mrows / 128);
    mma_out<<<g3, 256, OUT_SMEM>>>(oh, woh, out, b_out);
}